// round 1
// baseline (speedup 1.0000x reference)
#include <cuda_runtime.h>
#include <math.h>

#define NCTA 128
#define NTHREADS 256
#define BB 256            // batch
#define SS 2048           // sequence
#define NIN 128
#define HH 256
#define NOUT 128
#define K1 (NIN + HH)     // 384
#define KT 16
#define NT (K1 / KT)      // 24 tiles (0..7 from x, 8..23 from h)

// Persistent device state (allowed: __device__ globals, no cudaMalloc)
__device__ float g_XT[(size_t)SS * NIN * BB];   // [t][k][b]   268 MB
__device__ float g_h[2][HH * BB];               // [k][b] transposed h, double buffered
__device__ unsigned int g_bar_count;
__device__ unsigned int g_bar_gen;

__device__ __forceinline__ float gelu_exact(float x) {
    return 0.5f * x * (1.0f + erff(x * 0.70710678118654752f));
}

// ---------------- X transpose: X[b][t][k] -> g_XT[t][k][b] ----------------
__global__ void transpose_x_kernel(const float* __restrict__ X) {
    __shared__ float tile[32][33];
    int t  = blockIdx.z;
    int k0 = blockIdx.x * 32;
    int b0 = blockIdx.y * 32;
    int tx = threadIdx.x, ty = threadIdx.y;  // 32 x 8
    #pragma unroll
    for (int i = 0; i < 32; i += 8) {
        int b = b0 + ty + i;
        int k = k0 + tx;
        tile[ty + i][tx] = X[((size_t)b * SS + t) * NIN + k];
    }
    __syncthreads();
    #pragma unroll
    for (int i = 0; i < 32; i += 8) {
        int k = k0 + ty + i;
        int b = b0 + tx;
        g_XT[((size_t)t * NIN + k) * BB + b] = tile[tx][ty + i];
    }
}

// ---------------- main persistent kernel ----------------
__global__ void __launch_bounds__(NTHREADS, 1) rec_kernel(
    const float* __restrict__ W_ih, const float* __restrict__ b_ih,
    const float* __restrict__ W_ho, const float* __restrict__ b_ho,
    const float* __restrict__ gamma, const float* __restrict__ beta,
    float* __restrict__ out)
{
    extern __shared__ float smem[];
    float* sWT2 = smem;                      // [256][128] W_ho transposed: sWT2[k*128+n] = W_ho[n][k]
    float* sW1  = sWT2 + HH * NOUT;          // [2][384]  rows j0, j0+1 of W_ih
    float* sA   = sW1 + 2 * K1;              // [2][KT][256] staging (also reused as pp in phase2)
    float* sh   = sA + 2 * KT * BB;          // [2][256] h rows for phase2
    float* sred = sh + 2 * HH;               // reduction scratch (>= 40 floats)

    const int tid  = threadIdx.x;
    const int lane = tid & 31;
    const int wid  = tid >> 5;
    const int c    = blockIdx.x;
    const int j0   = 2 * c;    // phase1 columns
    const int r0   = 2 * c;    // phase2 output rows

    // ---- persistent preloads ----
    for (int i = tid; i < HH * NOUT; i += NTHREADS) {
        int k = i / NOUT, n = i % NOUT;
        sWT2[i] = W_ho[n * HH + k];
    }
    for (int i = tid; i < 2 * K1; i += NTHREADS)
        sW1[i] = W_ih[(j0 + i / K1) * K1 + (i % K1)];

    const float bih0 = b_ih[j0],     bih1 = b_ih[j0 + 1];
    const float ga0  = gamma[j0],    ga1  = gamma[j0 + 1];
    const float be0  = beta[j0],     be1  = beta[j0 + 1];
    const float bho  = b_ho[tid & 127];

    // barrier generation base (monotonic across graph replays; all CTAs read
    // the same value because gen can only advance after every CTA has arrived
    // at barrier #1, which is after this read in program order)
    __shared__ unsigned s_base;
    if (tid == 0) s_base = *(volatile unsigned*)&g_bar_gen;
    __syncthreads();
    const unsigned base = s_base;

    for (int t = 0; t < SS; ++t) {
        const float* __restrict__ hprev = g_h[t & 1];
        float* __restrict__       hnew  = g_h[(t & 1) ^ 1];
        const float* __restrict__ xt    = g_XT + (size_t)t * NIN * BB;

        // ================= Phase 1: z[:, j0..j0+1] =================
        float z0 = bih0, z1 = bih1;
        float4 v[4];

        // prologue: load tile 0
        {
            const float4* s4 = (const float4*)xt;
            #pragma unroll
            for (int i = 0; i < 4; ++i) v[i] = s4[i * 256 + tid];
            float4* d4 = (float4*)sA;
            #pragma unroll
            for (int i = 0; i < 4; ++i) d4[i * 256 + tid] = v[i];
        }
        __syncthreads();

        #pragma unroll 1
        for (int tile = 0; tile < NT; ++tile) {
            const int cur = tile & 1;
            if (tile + 1 < NT) {
                const float* src = (tile + 1 < 8) ? (xt + (tile + 1) * KT * BB)
                                                  : (hprev + (tile + 1 - 8) * KT * BB);
                const float4* s4 = (const float4*)src;
                #pragma unroll
                for (int i = 0; i < 4; ++i) v[i] = s4[i * 256 + tid];
            }
            // compute current tile
            {
                const float* a  = sA + cur * KT * BB;
                const float* w0 = sW1 + tile * KT;
                const float* w1 = sW1 + K1 + tile * KT;
                #pragma unroll
                for (int kk = 0; kk < KT; ++kk) {
                    float av = a[kk * BB + tid];
                    z0 = fmaf(av, w0[kk], z0);
                    z1 = fmaf(av, w1[kk], z1);
                }
            }
            if (tile + 1 < NT) {
                float4* d4 = (float4*)(sA + (cur ^ 1) * KT * BB);
                #pragma unroll
                for (int i = 0; i < 4; ++i) d4[i * 256 + tid] = v[i];
            }
            __syncthreads();
        }

        // ---- BatchNorm stats over batch (CTA-local: we own whole columns) ----
        float s0 = z0, q0 = z0 * z0, s1 = z1, q1 = z1 * z1;
        #pragma unroll
        for (int o = 16; o > 0; o >>= 1) {
            s0 += __shfl_down_sync(0xffffffffu, s0, o);
            q0 += __shfl_down_sync(0xffffffffu, q0, o);
            s1 += __shfl_down_sync(0xffffffffu, s1, o);
            q1 += __shfl_down_sync(0xffffffffu, q1, o);
        }
        if (lane == 0) {
            sred[wid]      = s0;
            sred[8 + wid]  = q0;
            sred[16 + wid] = s1;
            sred[24 + wid] = q1;
        }
        __syncthreads();
        if (tid == 0) {
            float S0 = 0.f, Q0 = 0.f, S1 = 0.f, Q1 = 0.f;
            #pragma unroll
            for (int w = 0; w < 8; ++w) {
                S0 += sred[w]; Q0 += sred[8 + w]; S1 += sred[16 + w]; Q1 += sred[24 + w];
            }
            float mu0 = S0 * (1.0f / BB);
            float mu1 = S1 * (1.0f / BB);
            float v0  = Q0 * (1.0f / BB) - mu0 * mu0;   // biased variance
            float v1  = Q1 * (1.0f / BB) - mu1 * mu1;
            sred[32] = mu0;
            sred[33] = rsqrtf(v0 + 1e-5f);
            sred[34] = mu1;
            sred[35] = rsqrtf(v1 + 1e-5f);
        }
        __syncthreads();
        {
            float mu0 = sred[32], rs0 = sred[33], mu1 = sred[34], rs1 = sred[35];
            float h0 = gelu_exact((z0 - mu0) * rs0 * ga0 + be0);
            float h1 = gelu_exact((z1 - mu1) * rs1 * ga1 + be1);
            hnew[j0 * BB + tid]       = h0;   // transposed layout [k][b], coalesced
            hnew[(j0 + 1) * BB + tid] = h1;
        }

        // ================= grid barrier (once per step) =================
        __syncthreads();
        if (tid == 0) {
            __threadfence();                       // release h writes to L2
            unsigned r = atomicAdd(&g_bar_count, 1);
            if (r == NCTA - 1) {
                g_bar_count = 0;
                __threadfence();
                atomicAdd(&g_bar_gen, 1);
            } else {
                unsigned target = base + (unsigned)t + 1u;
                while ((int)(*(volatile unsigned*)&g_bar_gen - target) < 0) {}
            }
            __threadfence();                       // acquire (CCTL.IVALL -> L1D flush)
        }
        __syncthreads();

        // ================= Phase 2: o[r0..r0+1, t, :] =================
        sh[tid]      = hnew[tid * BB + r0];        // h[r0][k],  k = tid
        sh[HH + tid] = hnew[tid * BB + r0 + 1];    // h[r0+1][k]
        __syncthreads();

        {
            const int n    = tid & 127;
            const int half = tid >> 7;             // k-half this thread reduces
            const int kb   = half * 128;
            float p0 = 0.f, p1 = 0.f;
            #pragma unroll 8
            for (int kk = 0; kk < 128; ++kk) {
                float w = sWT2[(kb + kk) * NOUT + n];
                p0 = fmaf(sh[kb + kk], w, p0);
                p1 = fmaf(sh[HH + kb + kk], w, p1);
            }
            float* pp = sA;                        // reuse staging buffer
            pp[half * 256 + n]       = p0;         // [half][row0][n]
            pp[half * 256 + 128 + n] = p1;         // [half][row1][n]
            __syncthreads();

            const int rr = tid >> 7;               // output row this thread finalizes
            float ov = pp[rr * 128 + n] + pp[256 + rr * 128 + n] + bho;
            ov = gelu_exact(ov);
            out[((size_t)(r0 + rr) * SS + t) * NOUT + n] = ov;
        }
        __syncthreads();   // protect sA reuse before next iteration's staging
    }
}

// ---------------- launch ----------------
extern "C" void kernel_launch(void* const* d_in, const int* in_sizes, int n_in,
                              void* d_out, int out_size) {
    const float* X     = (const float*)d_in[0];
    const float* W_ih  = (const float*)d_in[1];
    const float* b_ih  = (const float*)d_in[2];
    const float* W_ho  = (const float*)d_in[3];
    const float* b_ho  = (const float*)d_in[4];
    const float* gamma = (const float*)d_in[5];
    const float* beta  = (const float*)d_in[6];
    float* out = (float*)d_out;

    // zero h buffer 0 (h_{-1} = 0)
    void* hptr = nullptr;
    cudaGetSymbolAddress(&hptr, g_h);
    cudaMemsetAsync(hptr, 0, sizeof(float) * HH * BB, 0);

    // pre-transpose X into [t][k][b]
    dim3 tgrid(NIN / 32, BB / 32, SS);
    transpose_x_kernel<<<tgrid, dim3(32, 8)>>>(X);

    // persistent recurrence kernel
    const size_t smem_bytes =
        (HH * NOUT + 2 * K1 + 2 * KT * BB + 2 * HH + 64) * sizeof(float);
    cudaFuncSetAttribute(rec_kernel, cudaFuncAttributeMaxDynamicSharedMemorySize,
                         (int)smem_bytes);
    rec_kernel<<<NCTA, NTHREADS, smem_bytes>>>(W_ih, b_ih, W_ho, b_ho, gamma, beta, out);
}

// round 6
// speedup vs baseline: 1.6456x; 1.6456x over previous
#include <cuda_runtime.h>
#include <math.h>

#define NCTA 128
#define NTHREADS 256
#define BB 256            // batch
#define SS 2048           // sequence
#define NIN 128
#define HH 256
#define NOUT 128
#define KH 256            // recurrent K (h part only)
#define KT 16
#define NT (KH / KT)      // 16 tiles
#define NSTAGE 4
#define STAGE_FLOATS (KT * BB)   // 4096

// Persistent device state
__device__ __align__(16) float g_P[(size_t)SS * HH * BB];   // [t][j][b]  x@Wx.T + b_ih   (536 MB)
__device__ __align__(16) float g_h[2][HH * BB];             // [k][b] transposed h, double buffered
__device__ unsigned int g_bar_count;
__device__ unsigned int g_bar_gen;

__device__ __forceinline__ float gelu_exact(float x) {
    return 0.5f * x * (1.0f + erff(x * 0.70710678118654752f));
}

__device__ __forceinline__ void cp16(float* dst_smem, const float* src) {
    unsigned s = (unsigned)__cvta_generic_to_shared(dst_smem);
    asm volatile("cp.async.cg.shared.global [%0], [%1], 16;\n" :: "r"(s), "l"(src));
}
#define CP_COMMIT() asm volatile("cp.async.commit_group;\n" ::: "memory")
#define CP_WAIT3()  asm volatile("cp.async.wait_group 3;\n" ::: "memory")

// ================= Precompute P[t][j][b] = sum_k X[b][t][k] * W_ih[j][k] + b_ih[j] =================
// grid: (bblk=4, jblk=4, t=2048), block 256. Tile 64j x 64b, K=128.
#define PCS 68   // smem row stride (floats), 16B aligned, conflict-light
__global__ void __launch_bounds__(256, 1) precompute_P_kernel(
    const float* __restrict__ X, const float* __restrict__ W_ih,
    const float* __restrict__ b_ih)
{
    extern __shared__ float ps[];
    float* Ws = ps;                 // [128][PCS] -> Ws[k*PCS + j]
    float* Xs = ps + 128 * PCS;     // [128][PCS] -> Xs[k*PCS + b]

    const int tid = threadIdx.x;
    const int b0 = blockIdx.x * 64;
    const int j0 = blockIdx.y * 64;
    const int t  = blockIdx.z;

    // load W tile (transposed to [k][j])
    for (int e = tid; e < 64 * 128; e += 256) {
        int j = e >> 7, k = e & 127;
        Ws[k * PCS + j] = W_ih[(size_t)(j0 + j) * (NIN + HH) + k];
    }
    // load X tile (transposed to [k][b]); global reads coalesced along k
    for (int e = tid; e < 64 * 128; e += 256) {
        int b = e >> 7, k = e & 127;
        Xs[k * PCS + b] = X[((size_t)(b0 + b) * SS + t) * NIN + k];
    }
    __syncthreads();

    const int tx = tid & 15;    // b group
    const int ty = tid >> 4;    // j group
    float acc[4][4];
    #pragma unroll
    for (int i = 0; i < 4; ++i)
        #pragma unroll
        for (int jj = 0; jj < 4; ++jj) acc[jj][i] = 0.f;

    #pragma unroll 8
    for (int k = 0; k < 128; ++k) {
        float4 wv = *(const float4*)&Ws[k * PCS + ty * 4];
        float4 xv = *(const float4*)&Xs[k * PCS + tx * 4];
        acc[0][0] = fmaf(wv.x, xv.x, acc[0][0]);
        acc[0][1] = fmaf(wv.x, xv.y, acc[0][1]);
        acc[0][2] = fmaf(wv.x, xv.z, acc[0][2]);
        acc[0][3] = fmaf(wv.x, xv.w, acc[0][3]);
        acc[1][0] = fmaf(wv.y, xv.x, acc[1][0]);
        acc[1][1] = fmaf(wv.y, xv.y, acc[1][1]);
        acc[1][2] = fmaf(wv.y, xv.z, acc[1][2]);
        acc[1][3] = fmaf(wv.y, xv.w, acc[1][3]);
        acc[2][0] = fmaf(wv.z, xv.x, acc[2][0]);
        acc[2][1] = fmaf(wv.z, xv.y, acc[2][1]);
        acc[2][2] = fmaf(wv.z, xv.z, acc[2][2]);
        acc[2][3] = fmaf(wv.z, xv.w, acc[2][3]);
        acc[3][0] = fmaf(wv.w, xv.x, acc[3][0]);
        acc[3][1] = fmaf(wv.w, xv.y, acc[3][1]);
        acc[3][2] = fmaf(wv.w, xv.z, acc[3][2]);
        acc[3][3] = fmaf(wv.w, xv.w, acc[3][3]);
    }

    #pragma unroll
    for (int jj = 0; jj < 4; ++jj) {
        int j = j0 + ty * 4 + jj;
        float bj = b_ih[j];
        float4 r = make_float4(acc[jj][0] + bj, acc[jj][1] + bj,
                               acc[jj][2] + bj, acc[jj][3] + bj);
        *(float4*)&g_P[((size_t)t * HH + j) * BB + b0 + tx * 4] = r;
    }
}

// ================= main persistent kernel =================
__global__ void __launch_bounds__(NTHREADS, 1) rec_kernel(
    const float* __restrict__ W_ih, const float* __restrict__ W_ho,
    const float* __restrict__ b_ho,
    const float* __restrict__ gamma, const float* __restrict__ beta,
    float* __restrict__ out)
{
    extern __shared__ float smem[];
    float* sWT2   = smem;                        // [256][128] W_ho transposed
    float* sW1h   = sWT2 + HH * NOUT;            // [2][256] recurrent W rows j0,j0+1 (k=128..383)
    float* sh     = sW1h + 2 * KH;               // [2][256] h rows for phase2
    float* sred   = sh + 2 * HH;                 // 64 floats
    float* sStage = sred + 64;                   // [4][16][256] cp.async stages (64KB)

    const int tid  = threadIdx.x;
    const int lane = tid & 31;
    const int wid  = tid >> 5;
    const int c    = blockIdx.x;
    const int j0   = 2 * c;    // phase1 columns
    const int r0   = 2 * c;    // phase2 batch rows

    // persistent preloads
    for (int i = tid; i < HH * NOUT; i += NTHREADS) {
        int k = i / NOUT, n = i % NOUT;
        sWT2[i] = W_ho[n * HH + k];
    }
    for (int i = tid; i < 2 * KH; i += NTHREADS)
        sW1h[i] = W_ih[(size_t)(j0 + i / KH) * (NIN + HH) + NIN + (i % KH)];

    const float ga0 = gamma[j0], ga1 = gamma[j0 + 1];
    const float be0 = beta[j0],  be1 = beta[j0 + 1];
    const float bho = b_ho[tid & 127];

    __shared__ unsigned s_base;
    if (tid == 0) s_base = *(volatile unsigned*)&g_bar_gen;
    __syncthreads();
    const unsigned base = s_base;

    // prologue: prefetch tiles 0..2 of step 0 from g_h[0] (zeros) + P[0]
    {
        const float* hprev = g_h[0];
        #pragma unroll
        for (int p = 0; p < 3; ++p) {
            const float* src = hprev + p * STAGE_FLOATS;
            float* dst = sStage + p * STAGE_FLOATS;
            #pragma unroll
            for (int i = 0; i < 4; ++i)
                cp16(dst + (tid + i * 256) * 4, src + (tid + i * 256) * 4);
            CP_COMMIT();
        }
    }
    float pP0 = __ldg(&g_P[(size_t)j0 * BB + tid]);
    float pP1 = __ldg(&g_P[(size_t)(j0 + 1) * BB + tid]);

    for (int t = 0; t < SS; ++t) {
        const float* __restrict__ hprev = g_h[t & 1];
        float* __restrict__       hnew  = g_h[(t & 1) ^ 1];

        // ================= Phase 1: z[:, j0..j0+1] over K=256 (h part) =================
        float z0 = pP0, z1 = pP1;

        #pragma unroll 1
        for (int tile = 0; tile < NT; ++tile) {
            if (tile + 3 < NT) {
                const float* src = hprev + (tile + 3) * STAGE_FLOATS;
                float* dst = sStage + ((tile + 3) & 3) * STAGE_FLOATS;
                #pragma unroll
                for (int i = 0; i < 4; ++i)
                    cp16(dst + (tid + i * 256) * 4, src + (tid + i * 256) * 4);
            }
            // FIX: commit EVERY iteration. In the tail (tile+3 >= NT) this commits
            // an empty group, keeping wait_group 3's committed-group arithmetic
            // aligned so tile i's group is always retired before its compute.
            // (Previous version skipped the tail commits -> wait_group 3 returned
            // with tiles 13..15 still in flight -> stale k=208..255 -> rel_err 1e-1.)
            CP_COMMIT();
            CP_WAIT3();
            __syncthreads();

            const float* a = sStage + (tile & 3) * STAGE_FLOATS;
            const float4* w0v = (const float4*)(sW1h + (tile << 4));
            const float4* w1v = (const float4*)(sW1h + KH + (tile << 4));
            #pragma unroll
            for (int q = 0; q < 4; ++q) {
                float4 w0 = w0v[q];
                float4 w1 = w1v[q];
                float a0 = a[(q * 4 + 0) * BB + tid];
                float a1 = a[(q * 4 + 1) * BB + tid];
                float a2 = a[(q * 4 + 2) * BB + tid];
                float a3 = a[(q * 4 + 3) * BB + tid];
                z0 = fmaf(a0, w0.x, z0); z1 = fmaf(a0, w1.x, z1);
                z0 = fmaf(a1, w0.y, z0); z1 = fmaf(a1, w1.y, z1);
                z0 = fmaf(a2, w0.z, z0); z1 = fmaf(a2, w1.z, z1);
                z0 = fmaf(a3, w0.w, z0); z1 = fmaf(a3, w1.w, z1);
            }
            __syncthreads();
        }

        // ---- BatchNorm stats over batch (CTA-local) ----
        float s0 = z0, q0 = z0 * z0, s1 = z1, q1 = z1 * z1;
        #pragma unroll
        for (int o = 16; o > 0; o >>= 1) {
            s0 += __shfl_down_sync(0xffffffffu, s0, o);
            q0 += __shfl_down_sync(0xffffffffu, q0, o);
            s1 += __shfl_down_sync(0xffffffffu, s1, o);
            q1 += __shfl_down_sync(0xffffffffu, q1, o);
        }
        if (lane == 0) {
            sred[wid] = s0; sred[8 + wid] = q0; sred[16 + wid] = s1; sred[24 + wid] = q1;
        }
        __syncthreads();
        if (tid == 0) {
            float S0 = 0.f, Q0 = 0.f, S1 = 0.f, Q1 = 0.f;
            #pragma unroll
            for (int w = 0; w < 8; ++w) {
                S0 += sred[w]; Q0 += sred[8 + w]; S1 += sred[16 + w]; Q1 += sred[24 + w];
            }
            float mu0 = S0 * (1.0f / BB), mu1 = S1 * (1.0f / BB);
            float v0 = Q0 * (1.0f / BB) - mu0 * mu0;
            float v1 = Q1 * (1.0f / BB) - mu1 * mu1;
            sred[32] = mu0; sred[33] = rsqrtf(v0 + 1e-5f);
            sred[34] = mu1; sred[35] = rsqrtf(v1 + 1e-5f);
        }
        __syncthreads();
        {
            float mu0 = sred[32], rs0 = sred[33], mu1 = sred[34], rs1 = sred[35];
            float h0 = gelu_exact((z0 - mu0) * rs0 * ga0 + be0);
            float h1 = gelu_exact((z1 - mu1) * rs1 * ga1 + be1);
            hnew[j0 * BB + tid]       = h0;
            hnew[(j0 + 1) * BB + tid] = h1;
        }

        // ================= grid barrier (once per step) =================
        __syncthreads();
        if (tid == 0) {
            __threadfence();
            unsigned r = atomicAdd(&g_bar_count, 1);
            if (r == NCTA - 1) {
                g_bar_count = 0;
                __threadfence();
                atomicAdd(&g_bar_gen, 1);
            } else {
                unsigned target = base + (unsigned)t + 1u;
                while ((int)(*(volatile unsigned*)&g_bar_gen - target) < 0) {}
            }
            __threadfence();
        }
        __syncthreads();

        // ---- post-barrier: prefetch next step's tiles 0..2 + P[t+1] ----
        if (t + 1 < SS) {
            const float* hnext = hnew;   // next step's hprev
            #pragma unroll
            for (int p = 0; p < 3; ++p) {
                const float* src = hnext + p * STAGE_FLOATS;
                float* dst = sStage + p * STAGE_FLOATS;
                #pragma unroll
                for (int i = 0; i < 4; ++i)
                    cp16(dst + (tid + i * 256) * 4, src + (tid + i * 256) * 4);
                CP_COMMIT();
            }
            pP0 = __ldg(&g_P[((size_t)(t + 1) * HH + j0) * BB + tid]);
            pP1 = __ldg(&g_P[((size_t)(t + 1) * HH + j0 + 1) * BB + tid]);
        }

        // ================= Phase 2: out rows b = r0, r0+1 =================
        sh[tid]      = hnew[tid * BB + r0];
        sh[HH + tid] = hnew[tid * BB + r0 + 1];
        __syncthreads();
        {
            const int n    = tid & 127;
            const int half = tid >> 7;
            const int kb   = half * 128;
            float p0 = 0.f, p1 = 0.f;
            #pragma unroll 8
            for (int kk = 0; kk < 128; ++kk) {
                float w = sWT2[(kb + kk) * NOUT + n];
                p0 = fmaf(sh[kb + kk], w, p0);
                p1 = fmaf(sh[HH + kb + kk], w, p1);
            }
            float* pp = sStage + 3 * STAGE_FLOATS;   // stage 3 free here
            pp[half * 256 + n]       = p0;
            pp[half * 256 + 128 + n] = p1;
            __syncthreads();

            const int rr = tid >> 7;
            float ov = pp[rr * 128 + n] + pp[256 + rr * 128 + n] + bho;
            ov = gelu_exact(ov);
            out[((size_t)(r0 + rr) * SS + t) * NOUT + n] = ov;
        }
        __syncthreads();   // stage3 free again before next iter writes it
    }
}

// ---------------- launch ----------------
extern "C" void kernel_launch(void* const* d_in, const int* in_sizes, int n_in,
                              void* d_out, int out_size) {
    const float* X     = (const float*)d_in[0];
    const float* W_ih  = (const float*)d_in[1];
    const float* b_ih  = (const float*)d_in[2];
    const float* W_ho  = (const float*)d_in[3];
    const float* b_ho  = (const float*)d_in[4];
    const float* gamma = (const float*)d_in[5];
    const float* beta  = (const float*)d_in[6];
    float* out = (float*)d_out;

    // zero h buffer 0 (h_{-1} = 0)
    void* hptr = nullptr;
    cudaGetSymbolAddress(&hptr, g_h);
    cudaMemsetAsync(hptr, 0, sizeof(float) * HH * BB, 0);

    // precompute P = X @ Wx.T + b_ih
    {
        size_t psmem = 2u * 128 * PCS * sizeof(float);
        cudaFuncSetAttribute(precompute_P_kernel,
                             cudaFuncAttributeMaxDynamicSharedMemorySize, (int)psmem);
        dim3 pgrid(4, 4, SS);
        precompute_P_kernel<<<pgrid, 256, psmem>>>(X, W_ih, b_ih);
    }

    // persistent recurrence kernel
    const size_t smem_bytes =
        (HH * NOUT + 2 * KH + 2 * HH + 64 + NSTAGE * STAGE_FLOATS) * sizeof(float);
    cudaFuncSetAttribute(rec_kernel, cudaFuncAttributeMaxDynamicSharedMemorySize,
                         (int)smem_bytes);
    rec_kernel<<<NCTA, NTHREADS, smem_bytes>>>(W_ih, W_ho, b_ho, gamma, beta, out);
}

// round 8
// speedup vs baseline: 1.6895x; 1.0266x over previous
#include <cuda_runtime.h>
#include <math.h>

#define NCTA 128
#define NTHREADS 256
#define BB 256            // batch
#define SS 2048           // sequence
#define NIN 128
#define HH 256
#define NOUT 128
#define KH 256            // recurrent K (h part)
#define KT 32
#define NTILE (KH / KT)          // 8 tiles
#define STAGE_FLOATS (KT * BB)   // 8192 floats = 32KB
#define NSTAGE 4

// Persistent device state
__device__ __align__(16) float g_P[(size_t)SS * HH * BB];   // [t][j][b]  x@Wx.T + b_ih
__device__ __align__(16) float g_h[2][HH * BB];             // [k][b] transposed h, double buffered
__device__ unsigned int g_bar_count;
__device__ unsigned int g_bar_gen;

__device__ __forceinline__ float gelu_exact(float x) {
    return 0.5f * x * (1.0f + erff(x * 0.70710678118654752f));
}

__device__ __forceinline__ void cp16(float* dst_smem, const float* src) {
    unsigned s = (unsigned)__cvta_generic_to_shared(dst_smem);
    asm volatile("cp.async.cg.shared.global [%0], [%1], 16;\n" :: "r"(s), "l"(src));
}
#define CP_COMMIT() asm volatile("cp.async.commit_group;\n" ::: "memory")
#define CP_WAIT2()  asm volatile("cp.async.wait_group 2;\n" ::: "memory")

// ================= Precompute P[t][j][b] = sum_k X[b][t][k] * W_ih[j][k] + b_ih[j] =================
#define PCS 68
__global__ void __launch_bounds__(256, 1) precompute_P_kernel(
    const float* __restrict__ X, const float* __restrict__ W_ih,
    const float* __restrict__ b_ih)
{
    extern __shared__ float ps[];
    float* Ws = ps;                 // [128][PCS] -> Ws[k*PCS + j]
    float* Xs = ps + 128 * PCS;     // [128][PCS] -> Xs[k*PCS + b]

    const int tid = threadIdx.x;
    const int b0 = blockIdx.x * 64;
    const int j0 = blockIdx.y * 64;
    const int t  = blockIdx.z;

    for (int e = tid; e < 64 * 128; e += 256) {
        int j = e >> 7, k = e & 127;
        Ws[k * PCS + j] = W_ih[(size_t)(j0 + j) * (NIN + HH) + k];
    }
    for (int e = tid; e < 64 * 128; e += 256) {
        int b = e >> 7, k = e & 127;
        Xs[k * PCS + b] = X[((size_t)(b0 + b) * SS + t) * NIN + k];
    }
    __syncthreads();

    const int tx = tid & 15;
    const int ty = tid >> 4;
    float acc[4][4];
    #pragma unroll
    for (int i = 0; i < 4; ++i)
        #pragma unroll
        for (int jj = 0; jj < 4; ++jj) acc[jj][i] = 0.f;

    #pragma unroll 8
    for (int k = 0; k < 128; ++k) {
        float4 wv = *(const float4*)&Ws[k * PCS + ty * 4];
        float4 xv = *(const float4*)&Xs[k * PCS + tx * 4];
        acc[0][0] = fmaf(wv.x, xv.x, acc[0][0]);
        acc[0][1] = fmaf(wv.x, xv.y, acc[0][1]);
        acc[0][2] = fmaf(wv.x, xv.z, acc[0][2]);
        acc[0][3] = fmaf(wv.x, xv.w, acc[0][3]);
        acc[1][0] = fmaf(wv.y, xv.x, acc[1][0]);
        acc[1][1] = fmaf(wv.y, xv.y, acc[1][1]);
        acc[1][2] = fmaf(wv.y, xv.z, acc[1][2]);
        acc[1][3] = fmaf(wv.y, xv.w, acc[1][3]);
        acc[2][0] = fmaf(wv.z, xv.x, acc[2][0]);
        acc[2][1] = fmaf(wv.z, xv.y, acc[2][1]);
        acc[2][2] = fmaf(wv.z, xv.z, acc[2][2]);
        acc[2][3] = fmaf(wv.z, xv.w, acc[2][3]);
        acc[3][0] = fmaf(wv.w, xv.x, acc[3][0]);
        acc[3][1] = fmaf(wv.w, xv.y, acc[3][1]);
        acc[3][2] = fmaf(wv.w, xv.z, acc[3][2]);
        acc[3][3] = fmaf(wv.w, xv.w, acc[3][3]);
    }

    #pragma unroll
    for (int jj = 0; jj < 4; ++jj) {
        int j = j0 + ty * 4 + jj;
        float bj = b_ih[j];
        float4 r = make_float4(acc[jj][0] + bj, acc[jj][1] + bj,
                               acc[jj][2] + bj, acc[jj][3] + bj);
        *(float4*)&g_P[((size_t)t * HH + j) * BB + b0 + tx * 4] = r;
    }
}

// ================= main persistent kernel =================
// CTA c: z-columns j0=2c, 2c+1 (phase 1) and output column n0=c (fused phase 2).
// Step t streams h_{t-1}: z_t accumulates from it AND o_{t-1} accumulates from it.
__global__ void __launch_bounds__(NTHREADS, 1) rec_kernel(
    const float* __restrict__ W_ih, const float* __restrict__ W_ho,
    const float* __restrict__ b_ho,
    const float* __restrict__ gamma, const float* __restrict__ beta,
    float* __restrict__ out)
{
    extern __shared__ float smem[];
    float* sW1h   = smem;                 // [2][256] W_ih rows j0,j0+1, k=128..383
    float* sWo    = sW1h + 2 * KH;        // [256]    W_ho row n0
    float* sred   = sWo + KH;             // 64 floats
    float* sStage = sred + 64;            // [4][32][256] cp.async stages (128KB)

    const int tid  = threadIdx.x;
    const int lane = tid & 31;
    const int wid  = tid >> 5;
    const int c    = blockIdx.x;
    const int j0   = 2 * c;     // z columns
    const int n0   = c;         // output column

    // persistent preloads
    for (int i = tid; i < 2 * KH; i += NTHREADS)
        sW1h[i] = W_ih[(size_t)(j0 + (i >> 8)) * (NIN + HH) + NIN + (i & 255)];
    for (int i = tid; i < KH; i += NTHREADS)
        sWo[i] = W_ho[(size_t)n0 * HH + i];

    const float ga0 = gamma[j0], ga1 = gamma[j0 + 1];
    const float be0 = beta[j0],  be1 = beta[j0 + 1];
    const float bho = b_ho[n0];

    __shared__ unsigned s_base;
    if (tid == 0) s_base = *(volatile unsigned*)&g_bar_gen;
    __syncthreads();
    const unsigned base = s_base;

    // prologue: prefetch tiles 0..2 of step 0 from g_h[0] (zeros)
    {
        const float* hprev = g_h[0];
        #pragma unroll
        for (int p = 0; p < 3; ++p) {
            const float4* s4 = (const float4*)(hprev + p * STAGE_FLOATS);
            float* dst = sStage + p * STAGE_FLOATS;
            #pragma unroll
            for (int i = 0; i < 8; ++i)
                cp16(dst + (tid + i * 256) * 4, (const float*)(s4 + tid + i * 256));
            CP_COMMIT();
        }
    }
    float pP0 = __ldg(&g_P[(size_t)j0 * BB + tid]);
    float pP1 = __ldg(&g_P[(size_t)(j0 + 1) * BB + tid]);

    float oacc = 0.f;   // o_{t-1} accumulator (b = tid, column n0)

    // t = 0..SS-1: compute h_t (+ o_{t-1}); t = SS: epilogue, o_{SS-1} only
    for (int t = 0; t <= SS; ++t) {
        const float* __restrict__ hprev = g_h[t & 1];
        float* __restrict__       hnew  = g_h[(t & 1) ^ 1];

        float z0 = pP0, z1 = pP1;

        // ===== fused tile loop over K=256 (one __syncthreads per tile) =====
        #pragma unroll 1
        for (int tile = 0; tile < NTILE; ++tile) {
            CP_WAIT2();          // tile `tile` resident (groups beyond newest 2 done)
            __syncthreads();     // (a) data visible to all  (b) all threads done with stage tile-1

            if (tile + 3 < NTILE) {
                const float4* s4 = (const float4*)(hprev + (tile + 3) * STAGE_FLOATS);
                float* dst = sStage + ((tile + 3) & 3) * STAGE_FLOATS;
                #pragma unroll
                for (int i = 0; i < 8; ++i)
                    cp16(dst + (tid + i * 256) * 4, (const float*)(s4 + tid + i * 256));
            }
            CP_COMMIT();         // every iteration (empty in tail) keeps wait_group math aligned

            const float*  a   = sStage + (tile & 3) * STAGE_FLOATS;
            const float4* w0v = (const float4*)(sW1h + (tile << 5));
            const float4* w1v = (const float4*)(sW1h + KH + (tile << 5));
            const float4* wov = (const float4*)(sWo + (tile << 5));
            #pragma unroll
            for (int q = 0; q < 8; ++q) {
                float4 w0 = w0v[q];
                float4 w1 = w1v[q];
                float4 wo = wov[q];
                float a0 = a[(q * 4 + 0) * BB + tid];
                float a1 = a[(q * 4 + 1) * BB + tid];
                float a2 = a[(q * 4 + 2) * BB + tid];
                float a3 = a[(q * 4 + 3) * BB + tid];
                z0 = fmaf(a0, w0.x, z0); z1 = fmaf(a0, w1.x, z1); oacc = fmaf(a0, wo.x, oacc);
                z0 = fmaf(a1, w0.y, z0); z1 = fmaf(a1, w1.y, z1); oacc = fmaf(a1, wo.y, oacc);
                z0 = fmaf(a2, w0.z, z0); z1 = fmaf(a2, w1.z, z1); oacc = fmaf(a2, wo.z, oacc);
                z0 = fmaf(a3, w0.w, z0); z1 = fmaf(a3, w1.w, z1); oacc = fmaf(a3, wo.w, oacc);
            }
        }

        // ===== store o_{t-1} (complete: h_{t-1} fully streamed) =====
        if (t > 0) {
            float ov = gelu_exact(oacc + bho);
            out[((size_t)tid * SS + (t - 1)) * NOUT + n0] = ov;   // out[b][t-1][n0], b=tid
        }
        if (t == SS) break;      // epilogue done
        oacc = 0.f;

        // ===== BatchNorm over batch (CTA-local) + GELU + h write =====
        float s0 = z0, q0 = z0 * z0, s1 = z1, q1 = z1 * z1;
        #pragma unroll
        for (int o = 16; o > 0; o >>= 1) {
            s0 += __shfl_down_sync(0xffffffffu, s0, o);
            q0 += __shfl_down_sync(0xffffffffu, q0, o);
            s1 += __shfl_down_sync(0xffffffffu, s1, o);
            q1 += __shfl_down_sync(0xffffffffu, q1, o);
        }
        if (lane == 0) {
            sred[wid] = s0; sred[8 + wid] = q0; sred[16 + wid] = s1; sred[24 + wid] = q1;
        }
        __syncthreads();
        if (tid == 0) {
            float S0 = 0.f, Q0 = 0.f, S1 = 0.f, Q1 = 0.f;
            #pragma unroll
            for (int w = 0; w < 8; ++w) {
                S0 += sred[w]; Q0 += sred[8 + w]; S1 += sred[16 + w]; Q1 += sred[24 + w];
            }
            float mu0 = S0 * (1.0f / BB), mu1 = S1 * (1.0f / BB);
            float v0 = Q0 * (1.0f / BB) - mu0 * mu0;
            float v1 = Q1 * (1.0f / BB) - mu1 * mu1;
            sred[32] = mu0; sred[33] = rsqrtf(v0 + 1e-5f);
            sred[34] = mu1; sred[35] = rsqrtf(v1 + 1e-5f);
        }
        __syncthreads();
        {
            float mu0 = sred[32], rs0 = sred[33], mu1 = sred[34], rs1 = sred[35];
            float h0 = gelu_exact((z0 - mu0) * rs0 * ga0 + be0);
            float h1 = gelu_exact((z1 - mu1) * rs1 * ga1 + be1);
            hnew[j0 * BB + tid]       = h0;   // [k][b] layout, coalesced
            hnew[(j0 + 1) * BB + tid] = h1;
        }

        // ===== grid barrier (once per step) =====
        __syncthreads();
        if (tid == 0) {
            __threadfence();
            unsigned r = atomicAdd(&g_bar_count, 1);
            if (r == NCTA - 1) {
                g_bar_count = 0;
                __threadfence();
                atomicAdd(&g_bar_gen, 1);
            } else {
                unsigned target = base + (unsigned)t + 1u;
                while ((int)(*(volatile unsigned*)&g_bar_gen - target) < 0) {}
            }
            __threadfence();
        }
        __syncthreads();

        // ===== post-barrier: prefetch next step's tiles 0..2 (+ next P) =====
        {
            const float* hnext = hnew;       // next step's hprev
            #pragma unroll
            for (int p = 0; p < 3; ++p) {
                const float4* s4 = (const float4*)(hnext + p * STAGE_FLOATS);
                float* dst = sStage + p * STAGE_FLOATS;
                #pragma unroll
                for (int i = 0; i < 8; ++i)
                    cp16(dst + (tid + i * 256) * 4, (const float*)(s4 + tid + i * 256));
                CP_COMMIT();
            }
            if (t + 1 < SS) {
                pP0 = __ldg(&g_P[((size_t)(t + 1) * HH + j0) * BB + tid]);
                pP1 = __ldg(&g_P[((size_t)(t + 1) * HH + j0 + 1) * BB + tid]);
            }
        }
    }
}

// ---------------- launch ----------------
extern "C" void kernel_launch(void* const* d_in, const int* in_sizes, int n_in,
                              void* d_out, int out_size) {
    const float* X     = (const float*)d_in[0];
    const float* W_ih  = (const float*)d_in[1];
    const float* b_ih  = (const float*)d_in[2];
    const float* W_ho  = (const float*)d_in[3];
    const float* b_ho  = (const float*)d_in[4];
    const float* gamma = (const float*)d_in[5];
    const float* beta  = (const float*)d_in[6];
    float* out = (float*)d_out;

    // zero h buffer 0 (h_{-1} = 0)
    void* hptr = nullptr;
    cudaGetSymbolAddress(&hptr, g_h);
    cudaMemsetAsync(hptr, 0, sizeof(float) * HH * BB, 0);

    // precompute P = X @ Wx.T + b_ih
    {
        size_t psmem = 2u * 128 * PCS * sizeof(float);
        cudaFuncSetAttribute(precompute_P_kernel,
                             cudaFuncAttributeMaxDynamicSharedMemorySize, (int)psmem);
        dim3 pgrid(4, 4, SS);
        precompute_P_kernel<<<pgrid, 256, psmem>>>(X, W_ih, b_ih);
    }

    // persistent recurrence kernel
    const size_t smem_bytes =
        (2 * KH + KH + 64 + NSTAGE * STAGE_FLOATS) * sizeof(float);
    cudaFuncSetAttribute(rec_kernel, cudaFuncAttributeMaxDynamicSharedMemorySize,
                         (int)smem_bytes);
    rec_kernel<<<NCTA, NTHREADS, smem_bytes>>>(W_ih, W_ho, b_ho, gamma, beta, out);
}

// round 9
// speedup vs baseline: 2.7672x; 1.6379x over previous
#include <cuda_runtime.h>
#include <math.h>

#define NCTA 128
#define NTHREADS 1024
#define BB 256            // batch
#define SS 2048           // sequence
#define NIN 128
#define HH 256
#define NOUT 128
#define KH 256            // recurrent K (h part)
#define KPG 64            // k per group (4 groups)

// Persistent device state
__device__ __align__(16) float g_P[(size_t)SS * HH * BB];   // [t][j][b]  x@Wx.T + b_ih
__device__ __align__(16) float g_h[2][HH * BB];             // [k][b] transposed h, double buffered
__device__ unsigned int g_bar_count;
__device__ unsigned int g_bar_gen;

__device__ __forceinline__ float gelu_exact(float x) {
    return 0.5f * x * (1.0f + erff(x * 0.70710678118654752f));
}

// ================= Precompute P[t][j][b] = sum_k X[b][t][k] * W_ih[j][k] + b_ih[j] =================
#define PCS 68
__global__ void __launch_bounds__(256, 1) precompute_P_kernel(
    const float* __restrict__ X, const float* __restrict__ W_ih,
    const float* __restrict__ b_ih)
{
    extern __shared__ float ps[];
    float* Ws = ps;                 // [128][PCS] -> Ws[k*PCS + j]
    float* Xs = ps + 128 * PCS;     // [128][PCS] -> Xs[k*PCS + b]

    const int tid = threadIdx.x;
    const int b0 = blockIdx.x * 64;
    const int j0 = blockIdx.y * 64;
    const int t  = blockIdx.z;

    for (int e = tid; e < 64 * 128; e += 256) {
        int j = e >> 7, k = e & 127;
        Ws[k * PCS + j] = W_ih[(size_t)(j0 + j) * (NIN + HH) + k];
    }
    for (int e = tid; e < 64 * 128; e += 256) {
        int b = e >> 7, k = e & 127;
        Xs[k * PCS + b] = X[((size_t)(b0 + b) * SS + t) * NIN + k];
    }
    __syncthreads();

    const int tx = tid & 15;
    const int ty = tid >> 4;
    float acc[4][4];
    #pragma unroll
    for (int i = 0; i < 4; ++i)
        #pragma unroll
        for (int jj = 0; jj < 4; ++jj) acc[jj][i] = 0.f;

    #pragma unroll 8
    for (int k = 0; k < 128; ++k) {
        float4 wv = *(const float4*)&Ws[k * PCS + ty * 4];
        float4 xv = *(const float4*)&Xs[k * PCS + tx * 4];
        acc[0][0] = fmaf(wv.x, xv.x, acc[0][0]);
        acc[0][1] = fmaf(wv.x, xv.y, acc[0][1]);
        acc[0][2] = fmaf(wv.x, xv.z, acc[0][2]);
        acc[0][3] = fmaf(wv.x, xv.w, acc[0][3]);
        acc[1][0] = fmaf(wv.y, xv.x, acc[1][0]);
        acc[1][1] = fmaf(wv.y, xv.y, acc[1][1]);
        acc[1][2] = fmaf(wv.y, xv.z, acc[1][2]);
        acc[1][3] = fmaf(wv.y, xv.w, acc[1][3]);
        acc[2][0] = fmaf(wv.z, xv.x, acc[2][0]);
        acc[2][1] = fmaf(wv.z, xv.y, acc[2][1]);
        acc[2][2] = fmaf(wv.z, xv.z, acc[2][2]);
        acc[2][3] = fmaf(wv.z, xv.w, acc[2][3]);
        acc[3][0] = fmaf(wv.w, xv.x, acc[3][0]);
        acc[3][1] = fmaf(wv.w, xv.y, acc[3][1]);
        acc[3][2] = fmaf(wv.w, xv.z, acc[3][2]);
        acc[3][3] = fmaf(wv.w, xv.w, acc[3][3]);
    }

    #pragma unroll
    for (int jj = 0; jj < 4; ++jj) {
        int j = j0 + ty * 4 + jj;
        float bj = b_ih[j];
        float4 r = make_float4(acc[jj][0] + bj, acc[jj][1] + bj,
                               acc[jj][2] + bj, acc[jj][3] + bj);
        *(float4*)&g_P[((size_t)t * HH + j) * BB + b0 + tx * 4] = r;
    }
}

// ================= main persistent kernel =================
// 1024 threads: 4 k-groups x 256 b-threads. Group g accumulates partial
// z0/z1/oacc over k in [64g, 64g+64) with direct coalesced __ldcg of h.
// CTA c owns z-columns j0=2c,2c+1 and out-column n0=c (fused GEMM2).
__global__ void __launch_bounds__(NTHREADS, 1) rec_kernel(
    const float* __restrict__ W_ih, const float* __restrict__ W_ho,
    const float* __restrict__ b_ho,
    const float* __restrict__ gamma, const float* __restrict__ beta,
    float* __restrict__ out)
{
    __shared__ float sW0[KH];            // W_ih[j0][NIN+k]
    __shared__ float sW1[KH];            // W_ih[j0+1][NIN+k]
    __shared__ float sWo[KH];            // W_ho[n0][k]
    __shared__ float sPart[4 * BB * 3];  // [g][b][{z0,z1,o}]  12KB
    __shared__ float sred[40];
    __shared__ unsigned s_base;

    const int tid = threadIdx.x;
    const int g   = tid >> 8;      // k group 0..3
    const int b   = tid & 255;     // batch element
    const int c   = blockIdx.x;
    const int j0  = 2 * c;
    const int n0  = c;

    // preload weights
    if (tid < KH) {
        sW0[tid] = W_ih[(size_t)j0 * (NIN + HH) + NIN + tid];
        sW1[tid] = W_ih[(size_t)(j0 + 1) * (NIN + HH) + NIN + tid];
        sWo[tid] = W_ho[(size_t)n0 * HH + tid];
    }

    const float ga0 = gamma[j0], ga1 = gamma[j0 + 1];
    const float be0 = beta[j0],  be1 = beta[j0 + 1];
    const float bho = b_ho[n0];

    if (tid == 0) s_base = *(volatile unsigned*)&g_bar_gen;
    __syncthreads();
    const unsigned base = s_base;

    float pP0 = 0.f, pP1 = 0.f;
    if (tid < 256) {
        pP0 = __ldg(&g_P[(size_t)j0 * BB + tid]);
        pP1 = __ldg(&g_P[(size_t)(j0 + 1) * BB + tid]);
    }

    const int lane = tid & 31;
    const int wid  = tid >> 5;
    const int k0g  = g * KPG;

    // t = 0..SS-1: h_t and o_{t-1}; t = SS: epilogue (o_{SS-1} only)
    for (int t = 0; t <= SS; ++t) {
        const float* __restrict__ hprev = g_h[t & 1] + (size_t)k0g * BB;
        float* __restrict__       hnew  = g_h[(t & 1) ^ 1];

        // ===== partial GEMMs over this group's 64 k =====
        float z0 = 0.f, z1 = 0.f, oa = 0.f;
        #pragma unroll
        for (int kc = 0; kc < KPG; kc += 8) {
            float a0 = __ldcg(hprev + (kc + 0) * BB + b);
            float a1 = __ldcg(hprev + (kc + 1) * BB + b);
            float a2 = __ldcg(hprev + (kc + 2) * BB + b);
            float a3 = __ldcg(hprev + (kc + 3) * BB + b);
            float a4 = __ldcg(hprev + (kc + 4) * BB + b);
            float a5 = __ldcg(hprev + (kc + 5) * BB + b);
            float a6 = __ldcg(hprev + (kc + 6) * BB + b);
            float a7 = __ldcg(hprev + (kc + 7) * BB + b);
            const int kk = k0g + kc;
            float4 wA = *(const float4*)&sW0[kk];
            float4 wB = *(const float4*)&sW0[kk + 4];
            float4 uA = *(const float4*)&sW1[kk];
            float4 uB = *(const float4*)&sW1[kk + 4];
            float4 vA = *(const float4*)&sWo[kk];
            float4 vB = *(const float4*)&sWo[kk + 4];
            z0 = fmaf(a0, wA.x, z0); z1 = fmaf(a0, uA.x, z1); oa = fmaf(a0, vA.x, oa);
            z0 = fmaf(a1, wA.y, z0); z1 = fmaf(a1, uA.y, z1); oa = fmaf(a1, vA.y, oa);
            z0 = fmaf(a2, wA.z, z0); z1 = fmaf(a2, uA.z, z1); oa = fmaf(a2, vA.z, oa);
            z0 = fmaf(a3, wA.w, z0); z1 = fmaf(a3, uA.w, z1); oa = fmaf(a3, vA.w, oa);
            z0 = fmaf(a4, wB.x, z0); z1 = fmaf(a4, uB.x, z1); oa = fmaf(a4, vB.x, oa);
            z0 = fmaf(a5, wB.y, z0); z1 = fmaf(a5, uB.y, z1); oa = fmaf(a5, vB.y, oa);
            z0 = fmaf(a6, wB.z, z0); z1 = fmaf(a6, uB.z, z1); oa = fmaf(a6, vB.z, oa);
            z0 = fmaf(a7, wB.w, z0); z1 = fmaf(a7, uB.w, z1); oa = fmaf(a7, vB.w, oa);
        }

        // ===== merge 4 group partials =====
        {
            float* pp = &sPart[(g * BB + b) * 3];
            pp[0] = z0; pp[1] = z1; pp[2] = oa;
        }
        __syncthreads();

        if (tid < 256) {
            float Z0 = pP0, Z1 = pP1, O = 0.f;
            #pragma unroll
            for (int gg = 0; gg < 4; ++gg) {
                const float* pp = &sPart[(gg * BB + tid) * 3];
                Z0 += pp[0]; Z1 += pp[1]; O += pp[2];
            }

            // o_{t-1} (uses only hprev = h_{t-1}; complete now)
            if (t > 0)
                out[((size_t)tid * SS + (t - 1)) * NOUT + n0] = gelu_exact(O + bho);

            if (t < SS) {
                // BatchNorm over batch (CTA-local) + GELU + h write
                float s0 = Z0, q0 = Z0 * Z0, s1 = Z1, q1 = Z1 * Z1;
                #pragma unroll
                for (int o = 16; o > 0; o >>= 1) {
                    s0 += __shfl_down_sync(0xffffffffu, s0, o);
                    q0 += __shfl_down_sync(0xffffffffu, q0, o);
                    s1 += __shfl_down_sync(0xffffffffu, s1, o);
                    q1 += __shfl_down_sync(0xffffffffu, q1, o);
                }
                if (lane == 0) {
                    sred[wid] = s0; sred[8 + wid] = q0;
                    sred[16 + wid] = s1; sred[24 + wid] = q1;
                }
                __syncwarp();
                // reduce the 8 warp-partials within warp 0
                if (wid == 0) {
                    // wait for all 8 warps of group 0 via bar: use named barrier-free
                    // approach below (syncthreads covers all 1024 anyway)
                }
            }
        }
        __syncthreads();   // sred partials visible; also releases sPart for reuse

        if (t < SS) {
            if (tid == 0) {
                float S0 = 0.f, Q0 = 0.f, S1 = 0.f, Q1 = 0.f;
                #pragma unroll
                for (int w = 0; w < 8; ++w) {
                    S0 += sred[w]; Q0 += sred[8 + w];
                    S1 += sred[16 + w]; Q1 += sred[24 + w];
                }
                float mu0 = S0 * (1.0f / BB), mu1 = S1 * (1.0f / BB);
                float v0 = Q0 * (1.0f / BB) - mu0 * mu0;
                float v1 = Q1 * (1.0f / BB) - mu1 * mu1;
                sred[32] = mu0; sred[33] = rsqrtf(v0 + 1e-5f);
                sred[34] = mu1; sred[35] = rsqrtf(v1 + 1e-5f);
            }
            __syncthreads();

            if (tid < 256) {
                float Z0 = pP0, Z1 = pP1;
                #pragma unroll
                for (int gg = 0; gg < 4; ++gg) {
                    const float* pp = &sPart[(gg * BB + tid) * 3];
                    Z0 += pp[0]; Z1 += pp[1];
                }
                float mu0 = sred[32], rs0 = sred[33], mu1 = sred[34], rs1 = sred[35];
                float h0 = gelu_exact((Z0 - mu0) * rs0 * ga0 + be0);
                float h1 = gelu_exact((Z1 - mu1) * rs1 * ga1 + be1);
                hnew[j0 * BB + tid]       = h0;
                hnew[(j0 + 1) * BB + tid] = h1;
            }

            // ===== grid barrier =====
            __syncthreads();
            if (tid == 0) {
                __threadfence();
                unsigned r = atomicAdd(&g_bar_count, 1);
                if (r == NCTA - 1) {
                    g_bar_count = 0;
                    __threadfence();
                    atomicAdd(&g_bar_gen, 1);
                } else {
                    unsigned target = base + (unsigned)t + 1u;
                    while ((int)(*(volatile unsigned*)&g_bar_gen - target) < 0) {}
                }
                __threadfence();
            }
            __syncthreads();

            // prefetch next P
            if (tid < 256 && t + 1 < SS) {
                pP0 = __ldg(&g_P[((size_t)(t + 1) * HH + j0) * BB + tid]);
                pP1 = __ldg(&g_P[((size_t)(t + 1) * HH + j0 + 1) * BB + tid]);
            }
        }
    }
}

// ---------------- launch ----------------
extern "C" void kernel_launch(void* const* d_in, const int* in_sizes, int n_in,
                              void* d_out, int out_size) {
    const float* X     = (const float*)d_in[0];
    const float* W_ih  = (const float*)d_in[1];
    const float* b_ih  = (const float*)d_in[2];
    const float* W_ho  = (const float*)d_in[3];
    const float* b_ho  = (const float*)d_in[4];
    const float* gamma = (const float*)d_in[5];
    const float* beta  = (const float*)d_in[6];
    float* out = (float*)d_out;

    // zero h buffer 0 (h_{-1} = 0)
    void* hptr = nullptr;
    cudaGetSymbolAddress(&hptr, g_h);
    cudaMemsetAsync(hptr, 0, sizeof(float) * HH * BB, 0);

    // precompute P = X @ Wx.T + b_ih
    {
        size_t psmem = 2u * 128 * PCS * sizeof(float);
        cudaFuncSetAttribute(precompute_P_kernel,
                             cudaFuncAttributeMaxDynamicSharedMemorySize, (int)psmem);
        dim3 pgrid(4, 4, SS);
        precompute_P_kernel<<<pgrid, 256, psmem>>>(X, W_ih, b_ih);
    }

    // persistent recurrence kernel (static smem only)
    rec_kernel<<<NCTA, NTHREADS>>>(W_ih, W_ho, b_ho, gamma, beta, out);
}

// round 10
// speedup vs baseline: 2.9262x; 1.0575x over previous
#include <cuda_runtime.h>
#include <math.h>

#define NCTA 128
#define NTHREADS 1024
#define BB 256            // batch
#define SS 2048           // sequence
#define NIN 128
#define HH 256
#define NOUT 128
#define NG 8              // k-groups
#define KPG 32            // k per group

typedef unsigned long long ull;

// Persistent device state
__device__ __align__(16) float g_P[(size_t)SS * HH * BB];   // [t][j][b]  x@Wx.T + b_ih
__device__ __align__(16) float g_h[2][HH * BB];             // [k][b] transposed h, double buffered
__device__ unsigned int g_bar_count;
__device__ unsigned int g_bar_gen;

__device__ __forceinline__ float gelu_exact(float x) {
    return 0.5f * x * (1.0f + erff(x * 0.70710678118654752f));
}

// packed fp32x2 ops (sm_103a)
#define FMA2(acc, a, w) asm("fma.rn.f32x2 %0, %1, %2, %0;" : "+l"(acc) : "l"(a), "l"(w))
#define ADD2(acc, v)    asm("add.rn.f32x2 %0, %0, %1;"     : "+l"(acc) : "l"(v))

// ================= Precompute P[t][j][b] = sum_k X[b][t][k] * W_ih[j][k] + b_ih[j] =================
#define PCS 68
__global__ void __launch_bounds__(256, 1) precompute_P_kernel(
    const float* __restrict__ X, const float* __restrict__ W_ih,
    const float* __restrict__ b_ih)
{
    extern __shared__ float ps[];
    float* Ws = ps;                 // [128][PCS] -> Ws[k*PCS + j]
    float* Xs = ps + 128 * PCS;     // [128][PCS] -> Xs[k*PCS + b]

    const int tid = threadIdx.x;
    const int b0 = blockIdx.x * 64;
    const int j0 = blockIdx.y * 64;
    const int t  = blockIdx.z;

    for (int e = tid; e < 64 * 128; e += 256) {
        int j = e >> 7, k = e & 127;
        Ws[k * PCS + j] = W_ih[(size_t)(j0 + j) * (NIN + HH) + k];
    }
    for (int e = tid; e < 64 * 128; e += 256) {
        int b = e >> 7, k = e & 127;
        Xs[k * PCS + b] = X[((size_t)(b0 + b) * SS + t) * NIN + k];
    }
    __syncthreads();

    const int tx = tid & 15;
    const int ty = tid >> 4;
    float acc[4][4];
    #pragma unroll
    for (int i = 0; i < 4; ++i)
        #pragma unroll
        for (int jj = 0; jj < 4; ++jj) acc[jj][i] = 0.f;

    #pragma unroll 8
    for (int k = 0; k < 128; ++k) {
        float4 wv = *(const float4*)&Ws[k * PCS + ty * 4];
        float4 xv = *(const float4*)&Xs[k * PCS + tx * 4];
        acc[0][0] = fmaf(wv.x, xv.x, acc[0][0]);
        acc[0][1] = fmaf(wv.x, xv.y, acc[0][1]);
        acc[0][2] = fmaf(wv.x, xv.z, acc[0][2]);
        acc[0][3] = fmaf(wv.x, xv.w, acc[0][3]);
        acc[1][0] = fmaf(wv.y, xv.x, acc[1][0]);
        acc[1][1] = fmaf(wv.y, xv.y, acc[1][1]);
        acc[1][2] = fmaf(wv.y, xv.z, acc[1][2]);
        acc[1][3] = fmaf(wv.y, xv.w, acc[1][3]);
        acc[2][0] = fmaf(wv.z, xv.x, acc[2][0]);
        acc[2][1] = fmaf(wv.z, xv.y, acc[2][1]);
        acc[2][2] = fmaf(wv.z, xv.z, acc[2][2]);
        acc[2][3] = fmaf(wv.z, xv.w, acc[2][3]);
        acc[3][0] = fmaf(wv.w, xv.x, acc[3][0]);
        acc[3][1] = fmaf(wv.w, xv.y, acc[3][1]);
        acc[3][2] = fmaf(wv.w, xv.z, acc[3][2]);
        acc[3][3] = fmaf(wv.w, xv.w, acc[3][3]);
    }

    #pragma unroll
    for (int jj = 0; jj < 4; ++jj) {
        int j = j0 + ty * 4 + jj;
        float bj = b_ih[j];
        float4 r = make_float4(acc[jj][0] + bj, acc[jj][1] + bj,
                               acc[jj][2] + bj, acc[jj][3] + bj);
        *(float4*)&g_P[((size_t)t * HH + j) * BB + b0 + tx * 4] = r;
    }
}

// ================= main persistent kernel =================
// 1024 threads = 8 k-groups x 128 threads; thread (g, gt) owns batch pair
// b = {2gt, 2gt+1} and k range [32g, 32g+32). All math in packed f32x2.
// Tail specialization: group 0 -> z column j0, group 1 -> j0+1, group 2 -> o.
__global__ void __launch_bounds__(NTHREADS, 1) rec_kernel(
    const float* __restrict__ W_ih, const float* __restrict__ W_ho,
    const float* __restrict__ b_ho,
    const float* __restrict__ gamma, const float* __restrict__ beta,
    float* __restrict__ out)
{
    __shared__ __align__(16) ull sW0d[HH];   // {w,w} duplicated pairs
    __shared__ __align__(16) ull sW1d[HH];
    __shared__ __align__(16) ull sWod[HH];
    __shared__ ull sPZ0[NG * 128];           // per-group partials (f32x2 per b-pair)
    __shared__ ull sPZ1[NG * 128];
    __shared__ ull sPO [NG * 128];
    __shared__ float sred[32];
    __shared__ unsigned s_base;

    const int tid = threadIdx.x;
    const int g   = tid >> 7;       // k-group 0..7
    const int gt  = tid & 127;      // thread-in-group; owns b = 2gt, 2gt+1
    const int c   = blockIdx.x;
    const int j0  = 2 * c;
    const int n0  = c;
    const int k0g = g * KPG;

    // build duplicated weight pairs
    for (int k = tid; k < HH; k += NTHREADS) {
        unsigned w0 = __float_as_uint(W_ih[(size_t)j0 * (NIN + HH) + NIN + k]);
        unsigned w1 = __float_as_uint(W_ih[(size_t)(j0 + 1) * (NIN + HH) + NIN + k]);
        unsigned wo = __float_as_uint(W_ho[(size_t)n0 * HH + k]);
        sW0d[k] = ((ull)w0 << 32) | w0;
        sW1d[k] = ((ull)w1 << 32) | w1;
        sWod[k] = ((ull)wo << 32) | wo;
    }

    const float ga  = gamma[j0 + (g & 1)];   // used by groups 0/1 only
    const float be  = beta[j0 + (g & 1)];
    const float bho = b_ho[n0];

    if (tid == 0) s_base = *(volatile unsigned*)&g_bar_gen;
    __syncthreads();
    const unsigned base = s_base;

    // P for step 0 (groups 0/1 only; group g reads column j0+g)
    ull pPu = 0;
    if (g < 2)
        pPu = __ldg((const ull*)g_P + (size_t)(j0 + g) * 128 + gt);

    for (int t = 0; t <= SS; ++t) {
        const ull* __restrict__ hrow  = (const ull*)(g_h[t & 1]);       // [256][128] pairs
        float2*    __restrict__ hnew2 = (float2*)(g_h[(t & 1) ^ 1]);

        // ===== partial GEMMs over this group's 32 k (packed f32x2) =====
        ull z0 = 0ull, z1 = 0ull, oa = 0ull;
        #pragma unroll
        for (int kc = 0; kc < KPG; kc += 8) {
            ull a[8];
            #pragma unroll
            for (int i = 0; i < 8; ++i)
                a[i] = __ldcg(hrow + (size_t)(k0g + kc + i) * 128 + gt);
            #pragma unroll
            for (int i = 0; i < 8; i += 2) {
                const int k = k0g + kc + i;
                ulonglong2 w0 = *(const ulonglong2*)&sW0d[k];
                ulonglong2 w1 = *(const ulonglong2*)&sW1d[k];
                ulonglong2 wo = *(const ulonglong2*)&sWod[k];
                FMA2(z0, a[i],     w0.x);
                FMA2(z1, a[i],     w1.x);
                FMA2(oa, a[i],     wo.x);
                FMA2(z0, a[i + 1], w0.y);
                FMA2(z1, a[i + 1], w1.y);
                FMA2(oa, a[i + 1], wo.y);
            }
        }
        sPZ0[g * 128 + gt] = z0;
        sPZ1[g * 128 + gt] = z1;
        sPO [g * 128 + gt] = oa;
        __syncthreads();   // S1: partials visible

        // ===== group 2: o_{t-1} = gelu(h_{t-1} @ Wo + b) =====
        if (g == 2 && t > 0) {
            ull O = 0ull;
            #pragma unroll
            for (int gg = 0; gg < NG; ++gg) ADD2(O, sPO[gg * 128 + gt]);
            float2 of = *(float2*)&O;
            out[((size_t)(2 * gt)     * SS + (t - 1)) * NOUT + n0] = gelu_exact(of.x + bho);
            out[((size_t)(2 * gt + 1) * SS + (t - 1)) * NOUT + n0] = gelu_exact(of.y + bho);
        }
        if (t == SS) break;   // epilogue: only final o needed

        // ===== groups 0/1: merge own z column + BN stats =====
        float zl = 0.f, zh = 0.f;
        if (g < 2) {
            ull Zm = pPu;
            const ull* sp = (g == 0) ? sPZ0 : sPZ1;
            #pragma unroll
            for (int gg = 0; gg < NG; ++gg) ADD2(Zm, sp[gg * 128 + gt]);
            float2 zf = *(float2*)&Zm;
            zl = zf.x; zh = zf.y;
            float s = zl + zh;
            float q = zl * zl + zh * zh;
            #pragma unroll
            for (int o = 16; o > 0; o >>= 1) {
                s += __shfl_down_sync(0xffffffffu, s, o);
                q += __shfl_down_sync(0xffffffffu, q, o);
            }
            if ((gt & 31) == 0) {
                int w = gt >> 5;
                sred[(g * 4 + w) * 2 + 0] = s;
                sred[(g * 4 + w) * 2 + 1] = q;
            }
        }
        __syncthreads();   // S2: stats partials visible

        if (g < 2) {
            float S = 0.f, Q = 0.f;
            #pragma unroll
            for (int w = 0; w < 4; ++w) {
                S += sred[(g * 4 + w) * 2 + 0];
                Q += sred[(g * 4 + w) * 2 + 1];
            }
            float mu  = S * (1.0f / BB);
            float var = Q * (1.0f / BB) - mu * mu;   // biased
            float rs  = rsqrtf(var + 1e-5f);
            float h0 = gelu_exact((zl - mu) * rs * ga + be);
            float h1 = gelu_exact((zh - mu) * rs * ga + be);
            hnew2[(size_t)(j0 + g) * 128 + gt] = make_float2(h0, h1);
        }

        // ===== grid barrier =====
        __syncthreads();   // S3: h stores issued by groups 0/1
        if (tid == 0) {
            __threadfence();
            unsigned r = atomicAdd(&g_bar_count, 1);
            if (r == NCTA - 1) {
                g_bar_count = 0;
                __threadfence();
                atomicAdd(&g_bar_gen, 1);
            } else {
                unsigned target = base + (unsigned)t + 1u;
                while ((int)(*(volatile unsigned*)&g_bar_gen - target) < 0) {}
            }
            __threadfence();
        }
        // overlap with tid0 spin: prefetch next step's P
        if (g < 2 && t + 1 < SS)
            pPu = __ldg((const ull*)g_P + ((size_t)(t + 1) * HH + j0 + g) * 128 + gt);
        __syncthreads();   // S4: barrier passed
    }
}

// ---------------- launch ----------------
extern "C" void kernel_launch(void* const* d_in, const int* in_sizes, int n_in,
                              void* d_out, int out_size) {
    const float* X     = (const float*)d_in[0];
    const float* W_ih  = (const float*)d_in[1];
    const float* b_ih  = (const float*)d_in[2];
    const float* W_ho  = (const float*)d_in[3];
    const float* b_ho  = (const float*)d_in[4];
    const float* gamma = (const float*)d_in[5];
    const float* beta  = (const float*)d_in[6];
    float* out = (float*)d_out;

    // zero h buffer 0 (h_{-1} = 0)
    void* hptr = nullptr;
    cudaGetSymbolAddress(&hptr, g_h);
    cudaMemsetAsync(hptr, 0, sizeof(float) * HH * BB, 0);

    // precompute P = X @ Wx.T + b_ih
    {
        size_t psmem = 2u * 128 * PCS * sizeof(float);
        cudaFuncSetAttribute(precompute_P_kernel,
                             cudaFuncAttributeMaxDynamicSharedMemorySize, (int)psmem);
        dim3 pgrid(4, 4, SS);
        precompute_P_kernel<<<pgrid, 256, psmem>>>(X, W_ih, b_ih);
    }

    // persistent recurrence kernel (static smem only)
    rec_kernel<<<NCTA, NTHREADS>>>(W_ih, W_ho, b_ho, gamma, beta, out);
}